// round 2
// baseline (speedup 1.0000x reference)
#include <cuda_runtime.h>
#include <cuda_fp16.h>
#include <cstdint>

#define GRIDS 64
#define GP    65            // GRIDS + 1
#define ODIM  128
#define PDIM  64            // INPUT_DIM / 2
#define BATCH 16384
#define CELLS (GP * GP)     // 4225
#define BT    32            // batch tile per block

// fp16 transposed table: fp_t[p][cell][o], cell = ia*65 + ib
__device__ __half g_fpt[(size_t)PDIM * CELLS * ODIM];   // ~69 MB

// ---------------------------------------------------------------------------
// Kernel 1: transpose + fp32->fp16 convert.
// fp[ia][ib][o][p] (p contiguous)  ->  g_fpt[p][cell][o] (o contiguous)
// One block per cell (4225 blocks, 256 threads). smem 128x65 transpose tile.
// ---------------------------------------------------------------------------
__global__ __launch_bounds__(256) void kan_transpose(const float* __restrict__ fp) {
    __shared__ float tile[ODIM * (PDIM + 1)];   // [o][p], pad to 65 -> conflict-free
    const int cell = blockIdx.x;
    const float* src = fp + (size_t)cell * (ODIM * PDIM);

    for (int idx = threadIdx.x; idx < ODIM * PDIM; idx += 256) {
        int o = idx >> 6;          // /64
        int p = idx & 63;
        tile[o * (PDIM + 1) + p] = src[idx];   // coalesced read along p
    }
    __syncthreads();
    for (int idx = threadIdx.x; idx < ODIM * PDIM; idx += 256) {
        int p = idx >> 7;          // /128
        int o = idx & 127;
        g_fpt[((size_t)p * CELLS + cell) * ODIM + o] =
            __float2half_rn(tile[o * (PDIM + 1) + p]);   // coalesced write along o
    }
}

// ---------------------------------------------------------------------------
// Accumulate 8 fp16 values (one uint4 = 8 halves) scaled by w into acc[8].
// ---------------------------------------------------------------------------
__device__ __forceinline__ void acc8(float* acc, uint4 v, float w) {
    float2 f0 = __half22float2(*reinterpret_cast<const __half2*>(&v.x));
    float2 f1 = __half22float2(*reinterpret_cast<const __half2*>(&v.y));
    float2 f2 = __half22float2(*reinterpret_cast<const __half2*>(&v.z));
    float2 f3 = __half22float2(*reinterpret_cast<const __half2*>(&v.w));
    acc[0] += w * f0.x; acc[1] += w * f0.y;
    acc[2] += w * f1.x; acc[3] += w * f1.y;
    acc[4] += w * f2.x; acc[5] += w * f2.y;
    acc[6] += w * f3.x; acc[7] += w * f3.y;
}

// ---------------------------------------------------------------------------
// Kernel 2: main gather + bilinear reduction.
// Block: 512 threads = 16 o-groups (8 outputs each) x 32 batch columns.
// Grid: BATCH/BT = 512 blocks.
// ---------------------------------------------------------------------------
__global__ __launch_bounds__(512) void kan_main(const float* __restrict__ x,
                                                const float* __restrict__ borders,
                                                const float* __restrict__ invlen,
                                                float* __restrict__ out) {
    __shared__ float sb[GP];
    __shared__ float sl[GRIDS];
    __shared__ int   s_cell[BT];
    __shared__ float s_d1[BT], s_d2[BT];
    __shared__ float so[ODIM][BT + 1];   // epilogue transpose buffer

    const int t  = threadIdx.x;
    const int og = t & 15;     // o-group: owns outputs og*8 .. og*8+7
    const int bi = t >> 4;     // batch index within tile, 0..31
    const int b0 = blockIdx.x * BT;

    if (t < GP)                 sb[t] = borders[t];
    else if (t < GP + GRIDS)    sl[t - GP] = invlen[t - GP];

    float acc[8] = {0.f, 0.f, 0.f, 0.f, 0.f, 0.f, 0.f, 0.f};
    const __half* __restrict__ tab = g_fpt;
    const int oofs = og * 8;

    for (int p = 0; p < PDIM; ++p) {
        __syncthreads();   // protects sb/sl on iter 0; s_* reuse on later iters
        if (t < BT) {
            float v1 = x[(size_t)(2 * p) * BATCH + b0 + t];
            float v2 = x[(size_t)(2 * p + 1) * BATCH + b0 + t];

            float e1 = expf(-fabsf(v1));
            float c1 = (v1 > 0.f) ? (1.f - 0.5f * e1) : (0.5f * e1);
            int i1 = (int)(c1 * (float)GRIDS);
            i1 = i1 < 0 ? 0 : (i1 > GRIDS - 1 ? GRIDS - 1 : i1);
            float d1 = (v1 - sb[i1]) * sl[i1];

            float e2 = expf(-fabsf(v2));
            float c2 = (v2 > 0.f) ? (1.f - 0.5f * e2) : (0.5f * e2);
            int i2 = (int)(c2 * (float)GRIDS);
            i2 = i2 < 0 ? 0 : (i2 > GRIDS - 1 ? GRIDS - 1 : i2);
            float d2 = (v2 - sb[i2]) * sl[i2];

            s_cell[t] = i1 * GP + i2;
            s_d1[t] = d1;
            s_d2[t] = d2;
        }
        __syncthreads();

        const int   c  = s_cell[bi];
        const float d1 = s_d1[bi];
        const float d2 = s_d2[bi];
        const float w11 = d1 * d2;
        const float w10 = d1 - w11;
        const float w01 = d2 - w11;
        const float w00 = 1.f - d1 - w01;

        const __half* base = tab + ((size_t)p * CELLS + c) * ODIM + oofs;
        uint4 a0 = *reinterpret_cast<const uint4*>(base);                   // (i1,   i2  )
        uint4 a1 = *reinterpret_cast<const uint4*>(base + ODIM);            // (i1,   i2+1)
        uint4 a2 = *reinterpret_cast<const uint4*>(base + GP * ODIM);       // (i1+1, i2  )
        uint4 a3 = *reinterpret_cast<const uint4*>(base + (GP + 1) * ODIM); // (i1+1, i2+1)

        acc8(acc, a0, w00);
        acc8(acc, a1, w01);
        acc8(acc, a2, w10);
        acc8(acc, a3, w11);
    }

    // Epilogue: transpose through smem for coalesced 128B row stores.
    __syncthreads();
#pragma unroll
    for (int k = 0; k < 8; ++k) so[oofs + k][bi] = acc[k];
    __syncthreads();
    for (int idx = t; idx < ODIM * BT; idx += 512) {
        int o = idx >> 5;   // /32
        int j = idx & 31;
        out[(size_t)o * BATCH + b0 + j] = so[o][j];
    }
}

extern "C" void kernel_launch(void* const* d_in, const int* in_sizes, int n_in,
                              void* d_out, int out_size) {
    const float* x       = (const float*)d_in[0];
    const float* fp      = (const float*)d_in[1];
    const float* borders = (const float*)d_in[2];
    const float* invlen  = (const float*)d_in[3];
    float* out = (float*)d_out;

    kan_transpose<<<CELLS, 256>>>(fp);
    kan_main<<<BATCH / BT, 512>>>(x, borders, invlen, out);
}

// round 3
// speedup vs baseline: 1.6710x; 1.6710x over previous
#include <cuda_runtime.h>
#include <cuda_fp16.h>
#include <cstdint>

#define GRIDS 64
#define GP    65            // GRIDS + 1
#define ODIM  128
#define PDIM  64            // INPUT_DIM / 2
#define BATCH 16384
#define CELLS (GP * GP)     // 4225
#define BT    32            // batch tile per block

// fp16 transposed table: fp_t[p][cell][o], cell = ia*65 + ib
__device__ __half g_fpt[(size_t)PDIM * CELLS * ODIM];   // ~69 MB

// ---------------------------------------------------------------------------
// Kernel 1: transpose + fp32->fp16 convert. (unchanged from R2)
// ---------------------------------------------------------------------------
__global__ __launch_bounds__(256) void kan_transpose(const float* __restrict__ fp) {
    __shared__ float tile[ODIM * (PDIM + 1)];
    const int cell = blockIdx.x;
    const float* src = fp + (size_t)cell * (ODIM * PDIM);

    for (int idx = threadIdx.x; idx < ODIM * PDIM; idx += 256) {
        int o = idx >> 6;
        int p = idx & 63;
        tile[o * (PDIM + 1) + p] = src[idx];
    }
    __syncthreads();
    for (int idx = threadIdx.x; idx < ODIM * PDIM; idx += 256) {
        int p = idx >> 7;
        int o = idx & 127;
        g_fpt[((size_t)p * CELLS + cell) * ODIM + o] =
            __float2half_rn(tile[o * (PDIM + 1) + p]);
    }
}

// ---------------------------------------------------------------------------
// Accumulate 8 fp16 values (one uint4 = 8 halves) scaled by w into acc[8].
// ---------------------------------------------------------------------------
__device__ __forceinline__ void acc8(float* acc, uint4 v, float w) {
    float2 f0 = __half22float2(*reinterpret_cast<const __half2*>(&v.x));
    float2 f1 = __half22float2(*reinterpret_cast<const __half2*>(&v.y));
    float2 f2 = __half22float2(*reinterpret_cast<const __half2*>(&v.z));
    float2 f3 = __half22float2(*reinterpret_cast<const __half2*>(&v.w));
    acc[0] += w * f0.x; acc[1] += w * f0.y;
    acc[2] += w * f1.x; acc[3] += w * f1.y;
    acc[4] += w * f2.x; acc[5] += w * f2.y;
    acc[6] += w * f3.x; acc[7] += w * f3.y;
}

// ---------------------------------------------------------------------------
// Kernel 2: main gather + bilinear reduction, barrier-free main loop.
// Block: 512 threads = 16 o-groups (8 outputs each) x 32 batch columns.
// Prologue computes ALL indices/weights for the 64 p-slices up front; the
// main loop then only does broadcast LDS + 4 independent LDG.128 + FMA.
// ---------------------------------------------------------------------------
__global__ __launch_bounds__(512) void kan_main(const float* __restrict__ x,
                                                const float* __restrict__ borders,
                                                const float* __restrict__ invlen,
                                                float* __restrict__ out) {
    __shared__ float sb[GP];
    __shared__ float sl[GRIDS];
    __shared__ int   s_cell[PDIM][BT];
    __shared__ float s_d1[PDIM][BT];
    __shared__ float s_d2[PDIM][BT];
    __shared__ float so[ODIM][BT + 1];   // epilogue transpose buffer

    const int t  = threadIdx.x;
    const int og = t & 15;     // o-group: owns outputs og*8 .. og*8+7
    const int bi = t >> 4;     // batch index within tile, 0..31
    const int b0 = blockIdx.x * BT;

    if (t < GP)                 sb[t] = borders[t];
    else if (t < GP + GRIDS)    sl[t - GP] = invlen[t - GP];
    __syncthreads();

    // Prologue: indices + interpolation offsets for all (p, b) of this tile.
    for (int i = t; i < PDIM * BT; i += 512) {
        int p = i >> 5;        // /32
        int b = i & 31;
        float v1 = x[(size_t)(2 * p) * BATCH + b0 + b];
        float v2 = x[(size_t)(2 * p + 1) * BATCH + b0 + b];

        float e1 = expf(-fabsf(v1));
        float c1 = (v1 > 0.f) ? (1.f - 0.5f * e1) : (0.5f * e1);
        int i1 = (int)(c1 * (float)GRIDS);
        i1 = i1 < 0 ? 0 : (i1 > GRIDS - 1 ? GRIDS - 1 : i1);

        float e2 = expf(-fabsf(v2));
        float c2 = (v2 > 0.f) ? (1.f - 0.5f * e2) : (0.5f * e2);
        int i2 = (int)(c2 * (float)GRIDS);
        i2 = i2 < 0 ? 0 : (i2 > GRIDS - 1 ? GRIDS - 1 : i2);

        s_cell[p][b] = i1 * GP + i2;
        s_d1[p][b]   = (v1 - sb[i1]) * sl[i1];
        s_d2[p][b]   = (v2 - sb[i2]) * sl[i2];
    }
    __syncthreads();

    float acc[8] = {0.f, 0.f, 0.f, 0.f, 0.f, 0.f, 0.f, 0.f};
    const __half* __restrict__ tab = g_fpt;
    const int oofs = og * 8;

#pragma unroll 2
    for (int p = 0; p < PDIM; ++p) {
        const int   c  = s_cell[p][bi];
        const float d1 = s_d1[p][bi];
        const float d2 = s_d2[p][bi];
        const float w11 = d1 * d2;
        const float w10 = d1 - w11;
        const float w01 = d2 - w11;
        const float w00 = 1.f - d1 - w01;

        const __half* base = tab + ((size_t)p * CELLS + c) * ODIM + oofs;
        uint4 a0 = *reinterpret_cast<const uint4*>(base);                   // (i1,   i2  )
        uint4 a1 = *reinterpret_cast<const uint4*>(base + ODIM);            // (i1,   i2+1)
        uint4 a2 = *reinterpret_cast<const uint4*>(base + GP * ODIM);       // (i1+1, i2  )
        uint4 a3 = *reinterpret_cast<const uint4*>(base + (GP + 1) * ODIM); // (i1+1, i2+1)

        acc8(acc, a0, w00);
        acc8(acc, a1, w01);
        acc8(acc, a2, w10);
        acc8(acc, a3, w11);
    }

    // Epilogue: transpose through smem for coalesced 128B row stores.
    __syncthreads();
#pragma unroll
    for (int k = 0; k < 8; ++k) so[oofs + k][bi] = acc[k];
    __syncthreads();
    for (int idx = t; idx < ODIM * BT; idx += 512) {
        int o = idx >> 5;   // /32
        int j = idx & 31;
        out[(size_t)o * BATCH + b0 + j] = so[o][j];
    }
}

extern "C" void kernel_launch(void* const* d_in, const int* in_sizes, int n_in,
                              void* d_out, int out_size) {
    const float* x       = (const float*)d_in[0];
    const float* fp      = (const float*)d_in[1];
    const float* borders = (const float*)d_in[2];
    const float* invlen  = (const float*)d_in[3];
    float* out = (float*)d_out;

    kan_transpose<<<CELLS, 256>>>(fp);
    kan_main<<<BATCH / BT, 512>>>(x, borders, invlen, out);
}

// round 4
// speedup vs baseline: 2.0714x; 1.2396x over previous
#include <cuda_runtime.h>
#include <cuda_fp16.h>
#include <cstdint>

#define GRIDS 64
#define GP    65            // GRIDS + 1
#define ODIM  128
#define PDIM  64            // INPUT_DIM / 2
#define BATCH 16384
#define CELLS (GP * GP)     // 4225
#define BT    32            // batch tile per block

// fp16 transposed table: fp_t[p][cell][o], cell = ia*65 + ib
__device__ __half g_fpt[(size_t)PDIM * CELLS * ODIM];   // ~69 MB

// ---------------------------------------------------------------------------
// Kernel 1: transpose + fp32->fp16 convert, vectorized.
// fp[ia][ib][o][p] (p contiguous)  ->  g_fpt[p][cell][o] (o contiguous)
// One block per cell. float4 coalesced reads; packed half2 (32-bit) writes.
// ---------------------------------------------------------------------------
__global__ __launch_bounds__(256) void kan_transpose(const float* __restrict__ fp) {
    __shared__ float tile[ODIM * (PDIM + 1)];   // [o][p], pad 65 (odd)
    const int cell = blockIdx.x;
    const float4* src = reinterpret_cast<const float4*>(fp + (size_t)cell * (ODIM * PDIM));

    // Read: 2048 float4 (o-major, p contiguous)
    for (int idx = threadIdx.x; idx < (ODIM * PDIM) / 4; idx += 256) {
        int o  = idx >> 4;          // /16 float4 per o-row
        int p4 = (idx & 15) << 2;
        float4 v = src[idx];
        float* row = &tile[o * (PDIM + 1) + p4];
        row[0] = v.x; row[1] = v.y; row[2] = v.z; row[3] = v.w;
    }
    __syncthreads();

    // Write: packed half2 along o (32-bit coalesced stores)
    __half2* dst2 = reinterpret_cast<__half2*>(g_fpt);
    for (int idx = threadIdx.x; idx < (ODIM * PDIM) / 2; idx += 256) {
        int p  = idx >> 6;          // /64 half2 per (p,cell) row
        int o2 = idx & 63;
        float lo = tile[(2 * o2) * (PDIM + 1) + p];
        float hi = tile[(2 * o2 + 1) * (PDIM + 1) + p];
        dst2[((size_t)p * CELLS + cell) * (ODIM / 2) + o2] =
            __floats2half2_rn(lo, hi);
    }
}

// ---------------------------------------------------------------------------
// Kernel 2: main gather + bilinear reduction, barrier-free main loop,
// fp16 corner-combine (HFMA2 chain) with fp32 accumulation.
// Block: 512 threads = 16 o-groups (8 outputs each) x 32 batch columns.
// ---------------------------------------------------------------------------
__global__ __launch_bounds__(512) void kan_main(const float* __restrict__ x,
                                                const float* __restrict__ borders,
                                                const float* __restrict__ invlen,
                                                float* __restrict__ out) {
    __shared__ float sb[GP];
    __shared__ float sl[GRIDS];
    __shared__ int   s_cell[PDIM][BT];
    __shared__ float s_d1[PDIM][BT];
    __shared__ float s_d2[PDIM][BT];
    __shared__ float so[ODIM][BT + 1];   // epilogue transpose buffer

    const int t  = threadIdx.x;
    const int og = t & 15;     // o-group: owns outputs og*8 .. og*8+7
    const int bi = t >> 4;     // batch index within tile, 0..31
    const int b0 = blockIdx.x * BT;

    if (t < GP)                 sb[t] = borders[t];
    else if (t < GP + GRIDS)    sl[t - GP] = invlen[t - GP];
    __syncthreads();

    // Prologue: indices + interpolation offsets for all (p, b) of this tile.
    for (int i = t; i < PDIM * BT; i += 512) {
        int p = i >> 5;        // /32
        int b = i & 31;
        float v1 = x[(size_t)(2 * p) * BATCH + b0 + b];
        float v2 = x[(size_t)(2 * p + 1) * BATCH + b0 + b];

        float e1 = expf(-fabsf(v1));
        float c1 = (v1 > 0.f) ? (1.f - 0.5f * e1) : (0.5f * e1);
        int i1 = (int)(c1 * (float)GRIDS);
        i1 = i1 < 0 ? 0 : (i1 > GRIDS - 1 ? GRIDS - 1 : i1);

        float e2 = expf(-fabsf(v2));
        float c2 = (v2 > 0.f) ? (1.f - 0.5f * e2) : (0.5f * e2);
        int i2 = (int)(c2 * (float)GRIDS);
        i2 = i2 < 0 ? 0 : (i2 > GRIDS - 1 ? GRIDS - 1 : i2);

        s_cell[p][b] = i1 * GP + i2;
        s_d1[p][b]   = (v1 - sb[i1]) * sl[i1];
        s_d2[p][b]   = (v2 - sb[i2]) * sl[i2];
    }
    __syncthreads();

    float acc[8] = {0.f, 0.f, 0.f, 0.f, 0.f, 0.f, 0.f, 0.f};
    const __half* __restrict__ tab = g_fpt;
    const int oofs = og * 8;

#pragma unroll 2
    for (int p = 0; p < PDIM; ++p) {
        const int   c  = s_cell[p][bi];
        const float d1 = s_d1[p][bi];
        const float d2 = s_d2[p][bi];
        const float w11 = d1 * d2;
        const float w10 = d1 - w11;
        const float w01 = d2 - w11;
        const float w00 = 1.f - d1 - w01;

        const __half2 h00 = __float2half2_rn(w00);
        const __half2 h01 = __float2half2_rn(w01);
        const __half2 h10 = __float2half2_rn(w10);
        const __half2 h11 = __float2half2_rn(w11);

        const __half* base = tab + ((size_t)p * CELLS + c) * ODIM + oofs;
        uint4 a0 = *reinterpret_cast<const uint4*>(base);                   // (i1,   i2  )
        uint4 a1 = *reinterpret_cast<const uint4*>(base + ODIM);            // (i1,   i2+1)
        uint4 a2 = *reinterpret_cast<const uint4*>(base + GP * ODIM);       // (i1+1, i2  )
        uint4 a3 = *reinterpret_cast<const uint4*>(base + (GP + 1) * ODIM); // (i1+1, i2+1)

        const unsigned* u0 = &a0.x;
        const unsigned* u1 = &a1.x;
        const unsigned* u2 = &a2.x;
        const unsigned* u3 = &a3.x;
#pragma unroll
        for (int j = 0; j < 4; ++j) {
            __half2 v0 = *reinterpret_cast<const __half2*>(&u0[j]);
            __half2 v1 = *reinterpret_cast<const __half2*>(&u1[j]);
            __half2 v2 = *reinterpret_cast<const __half2*>(&u2[j]);
            __half2 v3 = *reinterpret_cast<const __half2*>(&u3[j]);
            __half2 s = __hmul2(h00, v0);
            s = __hfma2(h01, v1, s);
            s = __hfma2(h10, v2, s);
            s = __hfma2(h11, v3, s);
            float2 f = __half22float2(s);
            acc[2 * j]     += f.x;
            acc[2 * j + 1] += f.y;
        }
    }

    // Epilogue: transpose through smem for coalesced 128B row stores.
    __syncthreads();
#pragma unroll
    for (int k = 0; k < 8; ++k) so[oofs + k][bi] = acc[k];
    __syncthreads();
    for (int idx = t; idx < ODIM * BT; idx += 512) {
        int o = idx >> 5;   // /32
        int j = idx & 31;
        out[(size_t)o * BATCH + b0 + j] = so[o][j];
    }
}

extern "C" void kernel_launch(void* const* d_in, const int* in_sizes, int n_in,
                              void* d_out, int out_size) {
    const float* x       = (const float*)d_in[0];
    const float* fp      = (const float*)d_in[1];
    const float* borders = (const float*)d_in[2];
    const float* invlen  = (const float*)d_in[3];
    float* out = (float*)d_out;

    kan_transpose<<<CELLS, 256>>>(fp);
    kan_main<<<BATCH / BT, 512>>>(x, borders, invlen, out);
}